// round 11
// baseline (speedup 1.0000x reference)
#include <cuda_runtime.h>
#include <cuda_bf16.h>
#include <cstdint>

#define B_ 16
#define N_ 8732
#define C_ 81
#define NV4_ 2183            // N_/4, exact
#define ITER1_ 9             // ceil(NV4_/256)
#define TOPK_ 200
#define CONF_ 0.01f
#define NMS_ 0.45f

__device__ float g_probsT[B_ * C_ * N_];   // [B, C, N] softmax probs, transposed

// ---------------------------------------------------------------------------
// Bitwise replica of libdevice __nv_expf — immune to fast-math / contraction.
// ---------------------------------------------------------------------------
__device__ __forceinline__ float exp_rn(float a) {
    float f, r, j, s, t;
    int i, ia;
    j = fmaf(1.442695f, a, 12582912.f);
    j = __fsub_rn(j, 12582912.f);
    f = fmaf(j, -6.93145752e-1f, a);
    f = fmaf(j, -1.42860677e-6f, f);
    i = (int)j;
    r =         1.37805939e-3f;
    r = fmaf(r, f, 8.37312452e-3f);
    r = fmaf(r, f, 4.16695364e-2f);
    r = fmaf(r, f, 1.66664720e-1f);
    r = fmaf(r, f, 4.99999851e-1f);
    r = fmaf(r, f, 1.00000000e+0f);
    r = fmaf(r, f, 1.00000000e+0f);
    ia = (i > 0) ? 0 : 0x83000000;
    s = __int_as_float(0x7f000000 + ia);
    t = __int_as_float((i << 23) - ia);
    r = __fmul_rn(r, s);
    r = __fmul_rn(r, t);
    if (fabsf(a) >= 104.0f) r = (a > 0.0f) ? __int_as_float(0x7f800000) : 0.0f;
    return r;
}

// ---------------------------------------------------------------------------
// Kernel 1: softmax over C=81 per (b,n) row, write transposed [B,C,N]
// (bitwise-stable vs reference — do not perturb)
// ---------------------------------------------------------------------------
__global__ __launch_bounds__(1024) void softmax_T_kernel(const float* __restrict__ conf) {
    __shared__ float tile[32][81];
    int b    = blockIdx.y;
    int n0   = blockIdx.x * 32;
    int warp = threadIdx.x >> 5;
    int lane = threadIdx.x & 31;
    int n    = n0 + warp;

    if (n < N_) {
        const float* row = conf + ((size_t)(b * N_ + n)) * C_;
        float v0 = row[lane];
        float v1 = (lane + 32 < C_) ? row[lane + 32] : -1e30f;
        float v2 = (lane + 64 < C_) ? row[lane + 64] : -1e30f;
        float m = fmaxf(v0, fmaxf(v1, v2));
        #pragma unroll
        for (int o = 16; o; o >>= 1) m = fmaxf(m, __shfl_xor_sync(0xFFFFFFFFu, m, o));
        float e0 = exp_rn(__fsub_rn(v0, m));
        float e1 = (lane + 32 < C_) ? exp_rn(__fsub_rn(v1, m)) : 0.0f;
        float e2 = (lane + 64 < C_) ? exp_rn(__fsub_rn(v2, m)) : 0.0f;
        float s = __fadd_rn(__fadd_rn(e0, e1), e2);
        #pragma unroll
        for (int o = 16; o; o >>= 1) s = __fadd_rn(s, __shfl_xor_sync(0xFFFFFFFFu, s, o));
        float inv = __fdiv_rn(1.0f, s);
        tile[warp][lane] = __fmul_rn(e0, inv);
        if (lane + 32 < C_) tile[warp][lane + 32] = __fmul_rn(e1, inv);
        if (lane + 64 < C_) tile[warp][lane + 64] = __fmul_rn(e2, inv);
    }
    __syncthreads();

    for (int idx = threadIdx.x; idx < 32 * C_; idx += 1024) {
        int c  = idx >> 5;
        int nn = idx & 31;
        int ng = n0 + nn;
        if (ng < N_)
            g_probsT[((size_t)b * C_ + c) * N_ + ng] = tile[nn][c];
    }
}

// ---------------------------------------------------------------------------
// Kernel 2: per-(b, class!=0) top-200 + on-demand decode + IoU + NMS + output
// ---------------------------------------------------------------------------
__global__ __launch_bounds__(256, 8) void nms_kernel(const float* __restrict__ loc,
                                                     const float* __restrict__ anchors,
                                                     float* __restrict__ out) {
    __shared__ unsigned long long cand[1024];   // 8KB; aliases hist2 early
    __shared__ unsigned hist1[256];             // level-1: exponent bins
    __shared__ unsigned wtot[8];
    __shared__ float4   sbox [TOPK_];
    __shared__ float    svals[TOPK_];
    __shared__ float    sarea[TOPK_];
    __shared__ unsigned smask[TOPK_ * 7];
    __shared__ unsigned skeep[7];
    __shared__ int      sB1, sC1, sB2, sCount;

    unsigned* hist2 = (unsigned*)cand;          // 2048 mantissa bins = 8KB

    int task = blockIdx.x;
    int b    = task / (C_ - 1);
    int cls  = task % (C_ - 1) + 1;
    int t    = threadIdx.x;
    int lane = t & 31;
    int wid  = t >> 5;

    // cls==1 blocks zero their batch's class-0 output plane (200*5 floats)
    if (cls == 1) {
        float4* z = (float4*)(out + (size_t)b * C_ * TOPK_ * 5);
        if (t < TOPK_ * 5 / 4) z[t] = make_float4(0.f, 0.f, 0.f, 0.f);
    }

    const float4* prow4 = (const float4*)(g_probsT + ((size_t)b * C_ + cls) * N_);

    if (t < 7) skeep[t] = 0;
    if (t == 0) sCount = 0;
    hist1[t] = 0;
    __syncthreads();

    // ============ LEVEL 1: exponent histogram (bits>>23), warp-aggregated ======
    for (int it = 0; it < ITER1_; it++) {
        int i = t + it * 256;
        bool valid = (i < NV4_);
        float4 p = valid ? prow4[i] : make_float4(0.f, 0.f, 0.f, 0.f);
        unsigned bb[4] = {__float_as_uint(p.x), __float_as_uint(p.y),
                          __float_as_uint(p.z), __float_as_uint(p.w)};
        #pragma unroll
        for (int k = 0; k < 4; k++) {
            unsigned bin = valid ? (bb[k] >> 23) : 0x1FFu;
            unsigned m = __match_any_sync(0xFFFFFFFFu, bin);
            if (valid && lane == (__ffs(m) - 1))
                atomicAdd(&hist1[bin], (unsigned)__popc(m));
        }
    }
    __syncthreads();

    // level-1 cutoff: warp-shuffle suffix scan over 256 bins (bin = thread id)
    {
        unsigned my = hist1[t];
        unsigned x = my;
        #pragma unroll
        for (int off = 1; off < 32; off <<= 1) {
            unsigned v = __shfl_down_sync(0xFFFFFFFFu, x, off);
            if (lane + off < 32) x += v;
        }
        if (lane == 0) wtot[wid] = x;
        __syncthreads();
        unsigned above = 0;
        #pragma unroll
        for (int w = 0; w < 8; w++) above += (w > wid) ? wtot[w] : 0u;
        unsigned incl = x + above, excl = incl - my;
        if (excl < TOPK_ && TOPK_ <= incl) { sB1 = t; sC1 = (int)excl; }
    }
    __syncthreads();
    unsigned b1 = (unsigned)sB1;
    int need2 = TOPK_ - sC1;                    // in [1,200]

    // ============ LEVEL 2: mantissa bits[22:12] within exponent b1 =============
    for (int i = t; i < 2048; i += 256) hist2[i] = 0;
    __syncthreads();
    for (int i = t; i < NV4_; i += 256) {
        float4 p = prow4[i];
        unsigned bb[4] = {__float_as_uint(p.x), __float_as_uint(p.y),
                          __float_as_uint(p.z), __float_as_uint(p.w)};
        #pragma unroll
        for (int k = 0; k < 4; k++)
            if ((bb[k] >> 23) == b1)
                atomicAdd(&hist2[(bb[k] >> 12) & 0x7FFu], 1u);
    }
    __syncthreads();
    {
        unsigned my = 0;
        #pragma unroll
        for (int q = 0; q < 8; q++) my += hist2[t * 8 + q];
        unsigned x = my;
        #pragma unroll
        for (int off = 1; off < 32; off <<= 1) {
            unsigned v = __shfl_down_sync(0xFFFFFFFFu, x, off);
            if (lane + off < 32) x += v;
        }
        if (lane == 0) wtot[wid] = x;
        __syncthreads();
        unsigned above = 0;
        #pragma unroll
        for (int w = 0; w < 8; w++) above += (w > wid) ? wtot[w] : 0u;
        unsigned incl = x + above, excl = incl - my;
        if ((int)excl < need2 && need2 <= (int)incl) {
            int acc = (int)excl;
            for (int bin = t * 8 + 7; bin >= t * 8; bin--) {
                int h = (int)hist2[bin];
                if (acc + h >= need2) { sB2 = bin; break; }
                acc += h;
            }
        }
    }
    __syncthreads();

    // single-compare cutoff: candidates <=> bits >= cut32 (positive floats)
    unsigned cut32 = (b1 << 23) | ((unsigned)sB2 << 12);
    __syncthreads();   // hist2 (aliasing cand) fully consumed before collect

    // ============ Collect candidates: M ≈ 200 + O(1) ============
    for (int i = t; i < NV4_; i += 256) {
        float4 p = prow4[i];
        unsigned bits[4] = {__float_as_uint(p.x), __float_as_uint(p.y),
                            __float_as_uint(p.z), __float_as_uint(p.w)};
        #pragma unroll
        for (int k = 0; k < 4; k++) {
            if (bits[k] >= cut32) {
                int pos = atomicAdd(&sCount, 1);
                if (pos < 1024)
                    cand[pos] = ((unsigned long long)bits[k] << 32)
                              | (unsigned)(0xFFFFFFFFu - (unsigned)(4 * i + k));
            }
        }
    }
    __syncthreads();
    int M = sCount; if (M > 1024) M = 1024;

    // ============ Rank-by-count selection + on-demand box decode =============
    for (int i = t; i < M; i += 256) {
        unsigned long long key = cand[i];
        int r = 0;
        for (int j = 0; j < M; j++) r += (cand[j] > key);   // LDS broadcast
        if (r < TOPK_) {
            float v = __uint_as_float((unsigned)(key >> 32));
            unsigned n = 0xFFFFFFFFu - (unsigned)key;
            svals[r] = v;
            // decode box n (bitwise-identical to reference decode)
            float4 l = ((const float4*)loc)[(size_t)b * N_ + n];
            float4 a = ((const float4*)anchors)[n];
            float cx = __fadd_rn(a.x, __fmul_rn(__fmul_rn(l.x, 0.1f), a.z));
            float cy = __fadd_rn(a.y, __fmul_rn(__fmul_rn(l.y, 0.1f), a.w));
            float w_ = __fmul_rn(a.z, exp_rn(__fmul_rn(l.z, 0.2f)));
            float h_ = __fmul_rn(a.w, exp_rn(__fmul_rn(l.w, 0.2f)));
            float hw = __fmul_rn(w_, 0.5f);
            float hh = __fmul_rn(h_, 0.5f);
            float4 bx = make_float4(__fsub_rn(cx, hw), __fsub_rn(cy, hh),
                                    __fadd_rn(cx, hw), __fadd_rn(cy, hh));
            sbox[r] = bx;
            sarea[r] = __fmul_rn(__fsub_rn(bx.z, bx.x), __fsub_rn(bx.w, bx.y));
            if (v > CONF_) atomicOr(&skeep[r >> 5], 1u << (r & 31));
        }
    }
    // pre-zero smask (words J < I>>5 are never written by the tile phase)
    for (int i = t; i < TOPK_ * 7; i += 256) smask[i] = 0;
    __syncthreads();

    // ============ IoU: 28 upper-triangle 32x32 tiles over 8 warps =============
    // Tile (I,J), I<=J: lane owns row i=I*32+lane, loops j over J-block
    // (warp-uniform bounds, LDS broadcast). Each smask[i][J] word is owned by
    // exactly one tile. Diagonal tiles masked to j>i. Guard-band compare:
    // division only within ±2e-5 of the 0.45 boundary; exact fallback inside.
    {
        int k = 0;
        #pragma unroll
        for (int I = 0; I < 7; I++) {
            #pragma unroll
            for (int J = I; J < 7; J++, k++) {
                if ((k & 7) == wid) {
                    int i = I * 32 + lane;
                    bool rowvalid = (i < TOPK_);
                    int isafe = rowvalid ? i : 0;
                    float4 bi = sbox[isafe];
                    float  ai = sarea[isafe];
                    unsigned word = 0;
                    int jend = (J == 6) ? (TOPK_ - 192) : 32;   // warp-uniform
                    for (int jj = 0; jj < jend; jj++) {
                        int j = J * 32 + jj;
                        float4 bj = sbox[j];
                        float  aj = sarea[j];
                        float lx = fmaxf(bi.x, bj.x), ly = fmaxf(bi.y, bj.y);
                        float rx = fminf(bi.z, bj.z), ry = fminf(bi.w, bj.w);
                        float iw = fmaxf(__fsub_rn(rx, lx), 0.0f);
                        float ih = fmaxf(__fsub_rn(ry, ly), 0.0f);
                        float inter = __fmul_rn(iw, ih);
                        bool sup = false;
                        if (inter > 0.0f) {
                            float uni = __fsub_rn(__fadd_rn(ai, aj), inter);
                            float r45 = __fmul_rn(NMS_, uni);
                            if (uni >= 1e-10f) {
                                if (inter > __fmul_rn(r45, 1.00002f)) sup = true;
                                else if (inter >= __fmul_rn(r45, 0.99998f))
                                    sup = (__fdiv_rn(inter, fmaxf(uni, 1e-12f)) > NMS_);
                            } else {
                                sup = (__fdiv_rn(inter, fmaxf(uni, 1e-12f)) > NMS_);
                            }
                        }
                        if (sup) word |= (1u << jj);
                    }
                    if (I == J) word &= (0xFFFFFFFEu << lane);  // keep j > i
                    if (rowvalid) smask[i * 7 + J] = word;
                }
            }
        }
    }
    __syncthreads();

    // ============ Sequential NMS (exact scan semantics), ffs-skip =============
    if (t == 0) {
        unsigned kw[7];
        #pragma unroll
        for (int w = 0; w < 7; w++) kw[w] = skeep[w];
        for (int w = 0; w < 7; w++) {
            unsigned m = kw[w];
            while (m) {
                int bit = __ffs(m) - 1;
                int i = w * 32 + bit;
                #pragma unroll
                for (int w2 = 0; w2 < 7; w2++)
                    if (w2 >= w) kw[w2] &= ~smask[i * 7 + w2];
                m = kw[w] & (0xFFFFFFFEu << bit);
            }
        }
        #pragma unroll
        for (int w = 0; w < 7; w++) skeep[w] = kw[w];
    }
    __syncthreads();

    // ============ Output [200,5] rows ============
    if (t < TOPK_) {
        bool kp = (skeep[t >> 5] >> (t & 31)) & 1u;
        float* o = out + (((size_t)b * C_ + cls) * TOPK_ + t) * 5;
        float4 bx = sbox[t];
        o[0] = kp ? svals[t] : 0.0f;
        o[1] = kp ? bx.x : 0.0f;
        o[2] = kp ? bx.y : 0.0f;
        o[3] = kp ? bx.z : 0.0f;
        o[4] = kp ? bx.w : 0.0f;
    }
}

// ---------------------------------------------------------------------------
extern "C" void kernel_launch(void* const* d_in, const int* in_sizes, int n_in,
                              void* d_out, int out_size) {
    const float* loc     = (const float*)d_in[0];   // [B,N,4]
    const float* conf    = (const float*)d_in[1];   // [B,N,C]
    const float* anchors = (const float*)d_in[2];   // [N,4]
    float* out = (float*)d_out;                     // [B,C,200,5]

    dim3 g1((N_ + 31) / 32, B_);
    softmax_T_kernel<<<g1, 1024>>>(conf);

    nms_kernel<<<B_ * (C_ - 1), 256>>>(loc, anchors, out);
}

// round 12
// speedup vs baseline: 1.7878x; 1.7878x over previous
#include <cuda_runtime.h>
#include <cuda_bf16.h>
#include <cstdint>

#define B_ 16
#define N_ 8732
#define C_ 81
#define NV4_ 2183            // N_/4, exact
#define ITER1_ 9             // ceil(NV4_/256)
#define TOPK_ 200
#define CONF_ 0.01f
#define NMS_ 0.45f

__device__ float g_probsT[B_ * C_ * N_];   // [B, C, N] softmax probs, transposed

// upper-triangle 32x32 tile enumeration (28 tiles over a 7x7 block grid)
__constant__ int c_tI[28] = {0,0,0,0,0,0,0, 1,1,1,1,1,1, 2,2,2,2,2, 3,3,3,3, 4,4,4, 5,5, 6};
__constant__ int c_tJ[28] = {0,1,2,3,4,5,6, 1,2,3,4,5,6, 2,3,4,5,6, 3,4,5,6, 4,5,6, 5,6, 6};

// ---------------------------------------------------------------------------
// Bitwise replica of libdevice __nv_expf — immune to fast-math / contraction.
// ---------------------------------------------------------------------------
__device__ __forceinline__ float exp_rn(float a) {
    float f, r, j, s, t;
    int i, ia;
    j = fmaf(1.442695f, a, 12582912.f);
    j = __fsub_rn(j, 12582912.f);
    f = fmaf(j, -6.93145752e-1f, a);
    f = fmaf(j, -1.42860677e-6f, f);
    i = (int)j;
    r =         1.37805939e-3f;
    r = fmaf(r, f, 8.37312452e-3f);
    r = fmaf(r, f, 4.16695364e-2f);
    r = fmaf(r, f, 1.66664720e-1f);
    r = fmaf(r, f, 4.99999851e-1f);
    r = fmaf(r, f, 1.00000000e+0f);
    r = fmaf(r, f, 1.00000000e+0f);
    ia = (i > 0) ? 0 : 0x83000000;
    s = __int_as_float(0x7f000000 + ia);
    t = __int_as_float((i << 23) - ia);
    r = __fmul_rn(r, s);
    r = __fmul_rn(r, t);
    if (fabsf(a) >= 104.0f) r = (a > 0.0f) ? __int_as_float(0x7f800000) : 0.0f;
    return r;
}

// ---------------------------------------------------------------------------
// Kernel 1: softmax over C=81 per (b,n) row, write transposed [B,C,N]
// (bitwise-stable vs reference — do not perturb)
// ---------------------------------------------------------------------------
__global__ __launch_bounds__(1024) void softmax_T_kernel(const float* __restrict__ conf) {
    __shared__ float tile[32][81];
    int b    = blockIdx.y;
    int n0   = blockIdx.x * 32;
    int warp = threadIdx.x >> 5;
    int lane = threadIdx.x & 31;
    int n    = n0 + warp;

    if (n < N_) {
        const float* row = conf + ((size_t)(b * N_ + n)) * C_;
        float v0 = row[lane];
        float v1 = (lane + 32 < C_) ? row[lane + 32] : -1e30f;
        float v2 = (lane + 64 < C_) ? row[lane + 64] : -1e30f;
        float m = fmaxf(v0, fmaxf(v1, v2));
        #pragma unroll
        for (int o = 16; o; o >>= 1) m = fmaxf(m, __shfl_xor_sync(0xFFFFFFFFu, m, o));
        float e0 = exp_rn(__fsub_rn(v0, m));
        float e1 = (lane + 32 < C_) ? exp_rn(__fsub_rn(v1, m)) : 0.0f;
        float e2 = (lane + 64 < C_) ? exp_rn(__fsub_rn(v2, m)) : 0.0f;
        float s = __fadd_rn(__fadd_rn(e0, e1), e2);
        #pragma unroll
        for (int o = 16; o; o >>= 1) s = __fadd_rn(s, __shfl_xor_sync(0xFFFFFFFFu, s, o));
        float inv = __fdiv_rn(1.0f, s);
        tile[warp][lane] = __fmul_rn(e0, inv);
        if (lane + 32 < C_) tile[warp][lane + 32] = __fmul_rn(e1, inv);
        if (lane + 64 < C_) tile[warp][lane + 64] = __fmul_rn(e2, inv);
    }
    __syncthreads();

    for (int idx = threadIdx.x; idx < 32 * C_; idx += 1024) {
        int c  = idx >> 5;
        int nn = idx & 31;
        int ng = n0 + nn;
        if (ng < N_)
            g_probsT[((size_t)b * C_ + c) * N_ + ng] = tile[nn][c];
    }
}

// ---------------------------------------------------------------------------
// Kernel 2: per-(b, class!=0) top-200 + on-demand decode + IoU + NMS + output
// ---------------------------------------------------------------------------
__global__ __launch_bounds__(256, 8) void nms_kernel(const float* __restrict__ loc,
                                                     const float* __restrict__ anchors,
                                                     float* __restrict__ out) {
    __shared__ unsigned long long cand[1024];   // 8KB; aliases hist2 early
    __shared__ unsigned hist1[256];             // level-1: exponent bins
    __shared__ unsigned wtot[8];
    __shared__ float4   sbox [TOPK_];
    __shared__ float    svals[TOPK_];
    __shared__ float    sarea[TOPK_];
    __shared__ unsigned smask[TOPK_ * 7];
    __shared__ unsigned skeep[7];
    __shared__ int      sB1, sC1, sB2, sCount;

    unsigned* hist2 = (unsigned*)cand;          // 2048 mantissa bins = 8KB

    int task = blockIdx.x;
    int b    = task / (C_ - 1);
    int cls  = task % (C_ - 1) + 1;
    int t    = threadIdx.x;
    int lane = t & 31;
    int wid  = t >> 5;

    // cls==1 blocks zero their batch's class-0 output plane (200*5 floats)
    if (cls == 1) {
        float4* z = (float4*)(out + (size_t)b * C_ * TOPK_ * 5);
        if (t < TOPK_ * 5 / 4) z[t] = make_float4(0.f, 0.f, 0.f, 0.f);
    }

    const float4* prow4 = (const float4*)(g_probsT + ((size_t)b * C_ + cls) * N_);

    if (t < 7) skeep[t] = 0;
    if (t == 0) sCount = 0;
    hist1[t] = 0;
    __syncthreads();

    // ============ LEVEL 1: exponent histogram (bits>>23), warp-aggregated ======
    for (int it = 0; it < ITER1_; it++) {
        int i = t + it * 256;
        bool valid = (i < NV4_);
        float4 p = valid ? prow4[i] : make_float4(0.f, 0.f, 0.f, 0.f);
        unsigned bb[4] = {__float_as_uint(p.x), __float_as_uint(p.y),
                          __float_as_uint(p.z), __float_as_uint(p.w)};
        #pragma unroll
        for (int k = 0; k < 4; k++) {
            unsigned bin = valid ? (bb[k] >> 23) : 0x1FFu;
            unsigned m = __match_any_sync(0xFFFFFFFFu, bin);
            if (valid && lane == (__ffs(m) - 1))
                atomicAdd(&hist1[bin], (unsigned)__popc(m));
        }
    }
    __syncthreads();

    // level-1 cutoff: warp-shuffle suffix scan over 256 bins (bin = thread id)
    {
        unsigned my = hist1[t];
        unsigned x = my;
        #pragma unroll
        for (int off = 1; off < 32; off <<= 1) {
            unsigned v = __shfl_down_sync(0xFFFFFFFFu, x, off);
            if (lane + off < 32) x += v;
        }
        if (lane == 0) wtot[wid] = x;
        __syncthreads();
        unsigned above = 0;
        #pragma unroll
        for (int w = 0; w < 8; w++) above += (w > wid) ? wtot[w] : 0u;
        unsigned incl = x + above, excl = incl - my;
        if (excl < TOPK_ && TOPK_ <= incl) { sB1 = t; sC1 = (int)excl; }
    }
    __syncthreads();
    unsigned b1 = (unsigned)sB1;
    int need2 = TOPK_ - sC1;                    // in [1,200]

    // ============ LEVEL 2: mantissa bits[22:12] within exponent b1 =============
    for (int i = t; i < 2048; i += 256) hist2[i] = 0;
    __syncthreads();
    for (int i = t; i < NV4_; i += 256) {
        float4 p = prow4[i];
        unsigned bb[4] = {__float_as_uint(p.x), __float_as_uint(p.y),
                          __float_as_uint(p.z), __float_as_uint(p.w)};
        #pragma unroll
        for (int k = 0; k < 4; k++)
            if ((bb[k] >> 23) == b1)
                atomicAdd(&hist2[(bb[k] >> 12) & 0x7FFu], 1u);
    }
    __syncthreads();
    {
        unsigned my = 0;
        #pragma unroll
        for (int q = 0; q < 8; q++) my += hist2[t * 8 + q];
        unsigned x = my;
        #pragma unroll
        for (int off = 1; off < 32; off <<= 1) {
            unsigned v = __shfl_down_sync(0xFFFFFFFFu, x, off);
            if (lane + off < 32) x += v;
        }
        if (lane == 0) wtot[wid] = x;
        __syncthreads();
        unsigned above = 0;
        #pragma unroll
        for (int w = 0; w < 8; w++) above += (w > wid) ? wtot[w] : 0u;
        unsigned incl = x + above, excl = incl - my;
        if ((int)excl < need2 && need2 <= (int)incl) {
            int acc = (int)excl;
            for (int bin = t * 8 + 7; bin >= t * 8; bin--) {
                int h = (int)hist2[bin];
                if (acc + h >= need2) { sB2 = bin; break; }
                acc += h;
            }
        }
    }
    __syncthreads();

    // single-compare cutoff: candidates <=> bits >= cut32 (positive floats)
    unsigned cut32 = (b1 << 23) | ((unsigned)sB2 << 12);
    __syncthreads();   // hist2 (aliasing cand) fully consumed before collect

    // ============ Collect candidates: M ≈ 200 + O(1) ============
    for (int i = t; i < NV4_; i += 256) {
        float4 p = prow4[i];
        unsigned bits[4] = {__float_as_uint(p.x), __float_as_uint(p.y),
                            __float_as_uint(p.z), __float_as_uint(p.w)};
        #pragma unroll
        for (int k = 0; k < 4; k++) {
            if (bits[k] >= cut32) {
                int pos = atomicAdd(&sCount, 1);
                if (pos < 1024)
                    cand[pos] = ((unsigned long long)bits[k] << 32)
                              | (unsigned)(0xFFFFFFFFu - (unsigned)(4 * i + k));
            }
        }
    }
    __syncthreads();
    int M = sCount; if (M > 1024) M = 1024;

    // ============ Rank-by-count selection + on-demand box decode =============
    for (int i = t; i < M; i += 256) {
        unsigned long long key = cand[i];
        int r = 0;
        for (int j = 0; j < M; j++) r += (cand[j] > key);   // LDS broadcast
        if (r < TOPK_) {
            float v = __uint_as_float((unsigned)(key >> 32));
            unsigned n = 0xFFFFFFFFu - (unsigned)key;
            svals[r] = v;
            // decode box n (bitwise-identical to reference decode)
            float4 l = ((const float4*)loc)[(size_t)b * N_ + n];
            float4 a = ((const float4*)anchors)[n];
            float cx = __fadd_rn(a.x, __fmul_rn(__fmul_rn(l.x, 0.1f), a.z));
            float cy = __fadd_rn(a.y, __fmul_rn(__fmul_rn(l.y, 0.1f), a.w));
            float w_ = __fmul_rn(a.z, exp_rn(__fmul_rn(l.z, 0.2f)));
            float h_ = __fmul_rn(a.w, exp_rn(__fmul_rn(l.w, 0.2f)));
            float hw = __fmul_rn(w_, 0.5f);
            float hh = __fmul_rn(h_, 0.5f);
            float4 bx = make_float4(__fsub_rn(cx, hw), __fsub_rn(cy, hh),
                                    __fadd_rn(cx, hw), __fadd_rn(cy, hh));
            sbox[r] = bx;
            sarea[r] = __fmul_rn(__fsub_rn(bx.z, bx.x), __fsub_rn(bx.w, bx.y));
            if (v > CONF_) atomicOr(&skeep[r >> 5], 1u << (r & 31));
        }
    }
    // pre-zero smask (words with J < I are never written by the tile phase)
    for (int i = t; i < TOPK_ * 7; i += 256) smask[i] = 0;
    __syncthreads();

    // ============ IoU: 28 upper-triangle 32x32 tiles, warp k-strided ==========
    // Warp w executes tiles k = w, w+8, w+16, w+24 (runtime loop, single code
    // copy -> no unroll/predication blowup). Lane owns row i=I*32+lane; inner
    // j-loop over the J-block is warp-uniform (LDS broadcast). Each
    // smask[i][J] word is written by exactly one tile. Guard-band compare:
    // division only within ±2e-5 of the 0.45 boundary; exact fallback inside.
    for (int k = wid; k < 28; k += 8) {
        int I = c_tI[k], J = c_tJ[k];
        int i = I * 32 + lane;
        bool rowvalid = (i < TOPK_);
        int isafe = rowvalid ? i : 0;
        float4 bi = sbox[isafe];
        float  ai = sarea[isafe];
        unsigned word = 0;
        int jbase = J * 32;
        int jend  = (J == 6) ? (TOPK_ - 192) : 32;   // warp-uniform
        for (int jj = 0; jj < jend; jj++) {
            int j = jbase + jj;
            float4 bj = sbox[j];
            float  aj = sarea[j];
            float lx = fmaxf(bi.x, bj.x), ly = fmaxf(bi.y, bj.y);
            float rx = fminf(bi.z, bj.z), ry = fminf(bi.w, bj.w);
            float iw = fmaxf(__fsub_rn(rx, lx), 0.0f);
            float ih = fmaxf(__fsub_rn(ry, ly), 0.0f);
            float inter = __fmul_rn(iw, ih);
            bool sup = false;
            if (inter > 0.0f) {
                float uni = __fsub_rn(__fadd_rn(ai, aj), inter);
                float r45 = __fmul_rn(NMS_, uni);
                if (uni >= 1e-10f) {
                    if (inter > __fmul_rn(r45, 1.00002f)) sup = true;
                    else if (inter >= __fmul_rn(r45, 0.99998f))
                        sup = (__fdiv_rn(inter, fmaxf(uni, 1e-12f)) > NMS_);
                } else {
                    sup = (__fdiv_rn(inter, fmaxf(uni, 1e-12f)) > NMS_);
                }
            }
            if (sup) word |= (1u << jj);
        }
        if (I == J) word &= (0xFFFFFFFEu << lane);   // keep j > i
        if (rowvalid) smask[i * 7 + J] = word;
    }
    __syncthreads();

    // ============ Sequential NMS (exact scan semantics), ffs-skip =============
    if (t == 0) {
        unsigned kw[7];
        #pragma unroll
        for (int w = 0; w < 7; w++) kw[w] = skeep[w];
        for (int w = 0; w < 7; w++) {
            unsigned m = kw[w];
            while (m) {
                int bit = __ffs(m) - 1;
                int i = w * 32 + bit;
                #pragma unroll
                for (int w2 = 0; w2 < 7; w2++)
                    if (w2 >= w) kw[w2] &= ~smask[i * 7 + w2];
                m = kw[w] & (0xFFFFFFFEu << bit);
            }
        }
        #pragma unroll
        for (int w = 0; w < 7; w++) skeep[w] = kw[w];
    }
    __syncthreads();

    // ============ Output [200,5] rows ============
    if (t < TOPK_) {
        bool kp = (skeep[t >> 5] >> (t & 31)) & 1u;
        float* o = out + (((size_t)b * C_ + cls) * TOPK_ + t) * 5;
        float4 bx = sbox[t];
        o[0] = kp ? svals[t] : 0.0f;
        o[1] = kp ? bx.x : 0.0f;
        o[2] = kp ? bx.y : 0.0f;
        o[3] = kp ? bx.z : 0.0f;
        o[4] = kp ? bx.w : 0.0f;
    }
}

// ---------------------------------------------------------------------------
extern "C" void kernel_launch(void* const* d_in, const int* in_sizes, int n_in,
                              void* d_out, int out_size) {
    const float* loc     = (const float*)d_in[0];   // [B,N,4]
    const float* conf    = (const float*)d_in[1];   // [B,N,C]
    const float* anchors = (const float*)d_in[2];   // [N,4]
    float* out = (float*)d_out;                     // [B,C,200,5]

    dim3 g1((N_ + 31) / 32, B_);
    softmax_T_kernel<<<g1, 1024>>>(conf);

    nms_kernel<<<B_ * (C_ - 1), 256>>>(loc, anchors, out);
}